// round 14
// baseline (speedup 1.0000x reference)
#include <cuda_runtime.h>

typedef unsigned long long u64;

#define TABN 512
#define NPROD 5                 // block 0 = Pauli, blocks 1..4 = LUT quarters
#define CONSUMER_BLK 128

__device__ __align__(16) u64    gC[256];      // Pauli coeffs, duplicated (c,c)
__device__ __align__(16) float2 gTab[TABN];   // (value, slope) of sigmoid(MLP(q))
__device__ int gFlagC   = 0;                  // Pauli coeffs ready
__device__ int gFlagLUT = 0;                  // bit b-1 set when LUT block b done

// ---------------- packed f32x2 helpers --------------------------------------
__device__ __forceinline__ u64 pk(float lo, float hi) {
    u64 r; asm("mov.b64 %0, {%1, %2};" : "=l"(r) : "f"(lo), "f"(hi)); return r;
}
__device__ __forceinline__ void upk(float& lo, float& hi, u64 v) {
    asm("mov.b64 {%0, %1}, %2;" : "=f"(lo), "=f"(hi) : "l"(v));
}
__device__ __forceinline__ u64 fma2(u64 a, u64 b, u64 c) {
    u64 d; asm("fma.rn.f32x2 %0, %1, %2, %3;" : "=l"(d) : "l"(a), "l"(b), "l"(c));
    return d;
}
__device__ __forceinline__ int ldAcq(const int* p) {
    int v; asm volatile("ld.acquire.gpu.global.b32 %0, [%1];" : "=r"(v) : "l"(p) : "memory");
    return v;
}

// ---------------- fused kernel ----------------------------------------------
// 128-thread blocks: 512 consumer CTAs -> ~3.5 CTAs/SM (skew 4v3 = 1.33x
// instead of 2v1 = 2x with 256-thread blocks). No min-blocks clamp.
__global__ void __launch_bounds__(CONSUMER_BLK) qnn_fused(
        const float4* __restrict__ x4, float4* __restrict__ out4,
        const float* __restrict__ qw,
        const float* __restrict__ W1, const float* __restrict__ b1,
        const float* __restrict__ W2, const float* __restrict__ b2,
        const float* __restrict__ W3, const float* __restrict__ b3,
        const float* __restrict__ W4, const float* __restrict__ b4) {
    int tid = threadIdx.x;
    int bid = blockIdx.x;

    // ============================ PRODUCER: Pauli ============================
    if (bid == 0) {
        __shared__ float2 sTrig[16];      // (sin(qw/2), cos(qw/2))
        __shared__ float2 Ucol[16][16];   // Ucol[j][m] = U[m][j]
        __shared__ float2 Msh[16][16];

        if (tid < 16) {
            float s, c;
            sincosf(0.5f * qw[tid], &s, &c);
            sTrig[tid] = make_float2(s, c);
        }
        __syncthreads();

        {   // each thread evolves TWO columns: j0 = tid>>4 (0..7), j1 = j0+8
            int m = tid & 15;
            int j0 = tid >> 4;
            int laneHi = (tid & 31) & 16;
            float re0 = (m == j0) ? 1.f : 0.f, im0 = 0.f;
            float re1 = (m == j0 + 8) ? 1.f : 0.f, im1 = 0.f;
            for (int layer = 0; layer < 2; layer++) {
#pragma unroll
                for (int i = 0; i < 4; i++) {
                    int str = 8 >> i;
                    int bit = m & str;
                    {   // RY
                        float2 sc = sTrig[layer * 4 + i];
                        float s = sc.x, c = sc.y;
                        float p0r = __shfl_xor_sync(0xffffffffu, re0, str);
                        float p0i = __shfl_xor_sync(0xffffffffu, im0, str);
                        float p1r = __shfl_xor_sync(0xffffffffu, re1, str);
                        float p1i = __shfl_xor_sync(0xffffffffu, im1, str);
                        if (bit) {
                            re0 = fmaf(s, p0r, c * re0); im0 = fmaf(s, p0i, c * im0);
                            re1 = fmaf(s, p1r, c * re1); im1 = fmaf(s, p1i, c * im1);
                        } else {
                            re0 = fmaf(-s, p0r, c * re0); im0 = fmaf(-s, p0i, c * im0);
                            re1 = fmaf(-s, p1r, c * re1); im1 = fmaf(-s, p1i, c * im1);
                        }
                    }
                    {   // RZ — diagonal, no shuffle
                        float2 sc = sTrig[layer * 4 + i + 4];
                        float sz = sc.x, cz = sc.y;
                        float nr, ni;
                        if (bit) {
                            nr = re0 * cz - im0 * sz; ni = im0 * cz + re0 * sz;
                            re0 = nr; im0 = ni;
                            nr = re1 * cz - im1 * sz; ni = im1 * cz + re1 * sz;
                            re1 = nr; im1 = ni;
                        } else {
                            nr = re0 * cz + im0 * sz; ni = im0 * cz - re0 * sz;
                            re0 = nr; im0 = ni;
                            nr = re1 * cz + im1 * sz; ni = im1 * cz - re1 * sz;
                            re1 = nr; im1 = ni;
                        }
                    }
                }
                {   // composed CNOTs: src bits (a, b^a, c^b^a, d^c^b^a)
                    int a = (m >> 3) & 1, b = (m >> 2) & 1, c = (m >> 1) & 1, d = m & 1;
                    int P = (a << 3) | ((b ^ a) << 2) | ((c ^ b ^ a) << 1) | (d ^ c ^ b ^ a);
                    int src = laneHi | P;
                    re0 = __shfl_sync(0xffffffffu, re0, src);
                    im0 = __shfl_sync(0xffffffffu, im0, src);
                    re1 = __shfl_sync(0xffffffffu, re1, src);
                    im1 = __shfl_sync(0xffffffffu, im1, src);
                }
#pragma unroll
                for (int i = 0; i < 4; i++) {   // RX
                    int str = 8 >> i;
                    float2 sc = sTrig[layer * 4 + i + 8];
                    float s = sc.x, c = sc.y;
                    float p0r = __shfl_xor_sync(0xffffffffu, re0, str);
                    float p0i = __shfl_xor_sync(0xffffffffu, im0, str);
                    float p1r = __shfl_xor_sync(0xffffffffu, re1, str);
                    float p1i = __shfl_xor_sync(0xffffffffu, im1, str);
                    float nr, ni;
                    nr = fmaf(s, p0i, c * re0); ni = fmaf(-s, p0r, c * im0);
                    re0 = nr; im0 = ni;
                    nr = fmaf(s, p1i, c * re1); ni = fmaf(-s, p1r, c * im1);
                    re1 = nr; im1 = ni;
                }
            }
            Ucol[j0][m]     = make_float2(re0, im0);
            Ucol[j0 + 8][m] = make_float2(re1, im1);
        }
        __syncthreads();
        // M[j][k] = sum_m conj(U[m][j]) * z_m * U[m][k]  (2 pairs per thread)
#pragma unroll
        for (int rep = 0; rep < 2; rep++) {
            int pair = tid + rep * 128;
            int j = pair >> 4, k = pair & 15;
            float ar = 0.f, ai = 0.f;
#pragma unroll
            for (int m = 0; m < 16; m++) {
                float z = (m < 8) ? 1.f : -1.f;
                float2 uj = Ucol[j][m], uk = Ucol[k][m];
                ar += z * (uj.x * uk.x + uj.y * uk.y);
                ai += z * (uj.x * uk.y - uj.y * uk.x);
            }
            Msh[j][k] = make_float2(ar, ai);
        }
        __syncthreads();
        // c_a = Re(Tr(M P_a)) / 16  (proven branchy form, 2 a's per thread)
        for (int rep = 0; rep < 2; rep++) {
            int a = tid + rep * 128;
            float accr = 0.f;
            for (int j = 0; j < 16; j++) {
                int k = j;
                float cr = 1.f, ci = 0.f;
                for (int i = 0; i < 4; i++) {
                    int ai_ = (a >> (2 * (3 - i))) & 3;
                    int ji  = (j >> (3 - i)) & 1;
                    if (ai_ == 1) {
                        k ^= (1 << (3 - i));
                    } else if (ai_ == 2) {
                        k ^= (1 << (3 - i));
                        float nr, ni;
                        if (ji == 0) { nr = -ci; ni = cr; } else { nr = ci; ni = -cr; }
                        cr = nr; ci = ni;
                    } else if (ai_ == 3) {
                        if (ji) { cr = -cr; ci = -ci; }
                    }
                }
                float2 mm = Msh[j][k];
                accr += mm.x * cr - mm.y * ci;
            }
            float cv = accr * (1.0f / 16.0f);
            gC[a] = pk(cv, cv);
        }
        __syncthreads();
        __threadfence();
        if (tid == 0) atomicExch(&gFlagC, 1);
        return;
    }

    // ============================ PRODUCER: LUT ==============================
    if (bid < NPROD) {
        __shared__ float sW1[32], sB1[32], sW2[512], sB2[16];
        __shared__ float sW3[128], sB3[8], sW4[8], sB4;
        __shared__ float sv[130];

        if (tid < 32) { sW1[tid] = W1[tid]; sB1[tid] = b1[tid]; }
        for (int i = tid; i < 512; i += 128) sW2[i] = W2[i];
        if (tid < 16) sB2[tid] = b2[tid];
        sW3[tid] = W3[tid];
        if (tid < 8) { sB3[tid] = b3[tid]; sW4[tid] = W4[tid]; }
        if (tid == 0) sB4 = b4[0];
        __syncthreads();

        {   // 129 points -> 128 slopes; thread 127 evaluates 2 points
            int nEval = (tid == 127) ? 2 : 1;
            for (int e = 0; e < nEval; e++) {
                int li = tid + e;
                int i = (bid - 1) * 128 + li;
                float q = fmaf((float)i, 2.0f / (float)TABN, -1.0f);

                float acc2[16];
#pragma unroll
                for (int k = 0; k < 16; k++) acc2[k] = sB2[k];
#pragma unroll 4
                for (int j = 0; j < 32; j++) {
                    float h1j = fmaxf(fmaf(sW1[j], q, sB1[j]), 0.f);
#pragma unroll
                    for (int k = 0; k < 16; k++)
                        acc2[k] = fmaf(sW2[k * 32 + j], h1j, acc2[k]);
                }
                float acc3[8];
#pragma unroll
                for (int k = 0; k < 8; k++) acc3[k] = sB3[k];
#pragma unroll 4
                for (int j = 0; j < 16; j++) {
                    float h2j = fmaxf(acc2[j], 0.f);
#pragma unroll
                    for (int k = 0; k < 8; k++)
                        acc3[k] = fmaf(sW3[k * 16 + j], h2j, acc3[k]);
                }
                float o = sB4;
#pragma unroll
                for (int j = 0; j < 8; j++) o = fmaf(sW4[j], fmaxf(acc3[j], 0.f), o);
                sv[li] = 1.f / (1.f + expf(-o));
            }
        }
        __syncthreads();
        gTab[(bid - 1) * 128 + tid] = make_float2(sv[tid], sv[tid + 1] - sv[tid]);
        __syncthreads();
        __threadfence();
        if (tid == 0) atomicOr(&gFlagLUT, 1 << (bid - 1));
        return;
    }

    // ============================ CONSUMERS ==================================
    // 4 samples/thread: two independent packed f32x2 chains per thread.
    __shared__ __align__(16) ulonglong2 sC[128];

    int t = (bid - NPROD) * CONSUMER_BLK + tid;
    float4 xs0 = x4[4 * t];
    float4 xs1 = x4[4 * t + 1];
    float4 xs2 = x4[4 * t + 2];
    float4 xs3 = x4[4 * t + 3];

    // Bloch components per pair p, qubit i: [X,Y,Z] = [sin^2, -sin*cos, cos]
    u64 n[2][4][3];
#pragma unroll
    for (int p = 0; p < 2; p++) {
        float4 xa = (p == 0) ? xs0 : xs2;
        float4 xb = (p == 0) ? xs1 : xs3;
        float va[4] = {xa.x, xa.y, xa.z, xa.w};
        float vb[4] = {xb.x, xb.y, xb.z, xb.w};
#pragma unroll
        for (int i = 0; i < 4; i++) {
            float sa, ca, sb, cb;
            __sincosf(va[i], &sa, &ca);
            __sincosf(vb[i], &sb, &cb);
            n[p][i][0] = pk(sa * sa, sb * sb);
            n[p][i][1] = pk(-sa * ca, -sb * cb);
            n[p][i][2] = pk(ca, cb);
        }
    }

    // wait for Pauli coeffs (fast-trig producer finishes ~1.5us in)
    if (tid == 0) {
        while (ldAcq(&gFlagC) == 0) __nanosleep(64);
    }
    __syncthreads();
    sC[tid] = ((const ulonglong2*)gC)[tid];
    __syncthreads();

    // q = Pauli tensor contraction, two independent chains share coeff loads
    u64 Q0, Q1;
    {
        u64 acc0[2];
#pragma unroll
        for (int a0 = 0; a0 < 4; a0++) {
            u64 acc1[2];
#pragma unroll
            for (int a1 = 0; a1 < 4; a1++) {
                ulonglong2 cg[8];
#pragma unroll
                for (int a2 = 0; a2 < 4; a2++) {
                    int bidx = (a0 * 4 + a1) * 4 + a2;
                    cg[2 * a2]     = sC[2 * bidx];
                    cg[2 * a2 + 1] = sC[2 * bidx + 1];
                }
                u64 accA[2];
#pragma unroll
                for (int a2 = 0; a2 < 4; a2++) {
                    ulonglong2 c01 = cg[2 * a2];
                    ulonglong2 c23 = cg[2 * a2 + 1];
                    u64 s3a = fma2(c01.y, n[0][3][0], c01.x);
                    u64 s3b = fma2(c01.y, n[1][3][0], c01.x);
                    s3a = fma2(c23.x, n[0][3][1], s3a);
                    s3b = fma2(c23.x, n[1][3][1], s3b);
                    s3a = fma2(c23.y, n[0][3][2], s3a);
                    s3b = fma2(c23.y, n[1][3][2], s3b);
                    if (a2 == 0) { accA[0] = s3a; accA[1] = s3b; }
                    else {
                        accA[0] = fma2(s3a, n[0][2][a2 - 1], accA[0]);
                        accA[1] = fma2(s3b, n[1][2][a2 - 1], accA[1]);
                    }
                }
                if (a1 == 0) { acc1[0] = accA[0]; acc1[1] = accA[1]; }
                else {
                    acc1[0] = fma2(accA[0], n[0][1][a1 - 1], acc1[0]);
                    acc1[1] = fma2(accA[1], n[1][1][a1 - 1], acc1[1]);
                }
            }
            if (a0 == 0) { acc0[0] = acc1[0]; acc0[1] = acc1[1]; }
            else {
                acc0[0] = fma2(acc1[0], n[0][0][a0 - 1], acc0[0]);
                acc0[1] = fma2(acc1[1], n[1][0][a0 - 1], acc0[1]);
            }
        }
        Q0 = acc0[0]; Q1 = acc0[1];
    }

    float q0, q1, q2v, q3;
    upk(q0, q1, Q0);
    upk(q2v, q3, Q1);

    // wait for LUT: single-thread poll, then block-wide release
    if (tid == 0) {
        while ((ldAcq(&gFlagLUT) & 0xF) != 0xF) __nanosleep(64);
    }
    __syncthreads();

    float4 r;
    {
        float qs[4] = {q0, q1, q2v, q3};
        float rs[4];
#pragma unroll
        for (int s = 0; s < 4; s++) {
            float idxf = fmaf(qs[s], (float)(TABN / 2), (float)(TABN / 2));
            idxf = fminf(fmaxf(idxf, 0.f), (float)TABN - 0.0005f);
            float fi = floorf(idxf);
            int i = (int)fi;
            float fr = idxf - fi;
            float2 e = __ldg(&gTab[i]);
            rs[s] = fmaf(e.y, fr, e.x);
        }
        r.x = rs[0]; r.y = rs[1]; r.z = rs[2]; r.w = rs[3];
    }
    out4[t] = r;
}

// ---------------- launch ----------------------------------------------------
extern "C" void kernel_launch(void* const* d_in, const int* in_sizes, int n_in,
                              void* d_out, int out_size) {
    const float* x  = (const float*)d_in[0];
    const float* qw = (const float*)d_in[1];
    const float* W1 = (const float*)d_in[2];
    const float* b1 = (const float*)d_in[3];
    const float* W2 = (const float*)d_in[4];
    const float* b2 = (const float*)d_in[5];
    const float* W3 = (const float*)d_in[6];
    const float* b3 = (const float*)d_in[7];
    const float* W4 = (const float*)d_in[8];
    const float* b4 = (const float*)d_in[9];

    int nthreads = out_size / 4;                       // 4 samples per thread
    int nblocks  = NPROD + nthreads / CONSUMER_BLK;    // 5 producers + 512 consumers
    qnn_fused<<<nblocks, CONSUMER_BLK>>>((const float4*)x, (float4*)d_out, qw,
                                         W1, b1, W2, b2, W3, b3, W4, b4);
}

// round 15
// speedup vs baseline: 2.0863x; 2.0863x over previous
#include <cuda_runtime.h>

typedef unsigned long long u64;

#define TABN 512
#define NPROD 5                 // block 0 = Pauli, blocks 1..4 = LUT quarters
#define CONSUMER_BLK 256

__device__ __align__(16) u64    gC[256];      // Pauli coeffs, duplicated (c,c)
__device__ __align__(16) float2 gTab[TABN];   // (value, slope) of sigmoid(MLP(q))
__device__ int gFlagC   = 0;                  // Pauli coeffs ready
__device__ int gFlagLUT = 0;                  // bit b-1 set when LUT block b done

// ---------------- packed f32x2 helpers --------------------------------------
__device__ __forceinline__ u64 pk(float lo, float hi) {
    u64 r; asm("mov.b64 %0, {%1, %2};" : "=l"(r) : "f"(lo), "f"(hi)); return r;
}
__device__ __forceinline__ void upk(float& lo, float& hi, u64 v) {
    asm("mov.b64 {%0, %1}, %2;" : "=f"(lo), "=f"(hi) : "l"(v));
}
__device__ __forceinline__ u64 fma2(u64 a, u64 b, u64 c) {
    u64 d; asm("fma.rn.f32x2 %0, %1, %2, %3;" : "=l"(d) : "l"(a), "l"(b), "l"(c));
    return d;
}
__device__ __forceinline__ int ldAcq(const int* p) {
    int v; asm volatile("ld.acquire.gpu.global.b32 %0, [%1];" : "=r"(v) : "l"(p) : "memory");
    return v;
}

// ---------------- fused kernel ----------------------------------------------
// 8 samples/thread, 128 consumer blocks + 5 producers = 133 blocks <= 148 SMs:
// one CTA per SM, single perfectly-balanced wave. No min-blocks clamp (the
// 4-chain consumer needs ~160 regs; clamping would spill — R4/R6/R14 lesson).
__global__ void __launch_bounds__(CONSUMER_BLK) qnn_fused(
        const float4* __restrict__ x4, float4* __restrict__ out4,
        const float* __restrict__ qw,
        const float* __restrict__ W1, const float* __restrict__ b1,
        const float* __restrict__ W2, const float* __restrict__ b2,
        const float* __restrict__ W3, const float* __restrict__ b3,
        const float* __restrict__ W4, const float* __restrict__ b4) {
    int tid = threadIdx.x;
    int bid = blockIdx.x;

    // ============================ PRODUCER: Pauli ============================
    if (bid == 0) {
        __shared__ float2 sTrig[16];      // (sin(qw/2), cos(qw/2))
        __shared__ float2 Ucol[16][16];   // Ucol[j][m] = U[m][j]
        __shared__ float2 Msh[16][16];

        if (tid < 16) {
            float s, c;
            sincosf(0.5f * qw[tid], &s, &c);
            sTrig[tid] = make_float2(s, c);
        }
        __syncthreads();

        {
            int j = tid >> 4, m = tid & 15;
            int laneHi = (tid & 31) & 16;
            float re = (m == j) ? 1.f : 0.f;
            float im = 0.f;
            for (int layer = 0; layer < 2; layer++) {
#pragma unroll
                for (int i = 0; i < 4; i++) {
                    int str = 8 >> i;
                    int bit = m & str;
                    {   // RY
                        float2 sc = sTrig[layer * 4 + i];
                        float s = sc.x, c = sc.y;
                        float pre = __shfl_xor_sync(0xffffffffu, re, str);
                        float pim = __shfl_xor_sync(0xffffffffu, im, str);
                        if (bit) { re = fmaf(s, pre, c * re); im = fmaf(s, pim, c * im); }
                        else     { re = fmaf(-s, pre, c * re); im = fmaf(-s, pim, c * im); }
                    }
                    {   // RZ — diagonal, no shuffle
                        float2 sc = sTrig[layer * 4 + i + 4];
                        float sz = sc.x, cz = sc.y;
                        float nr, ni;
                        if (bit) { nr = re * cz - im * sz; ni = im * cz + re * sz; }
                        else     { nr = re * cz + im * sz; ni = im * cz - re * sz; }
                        re = nr; im = ni;
                    }
                }
                {   // composed CNOTs: src bits (a, b^a, c^b^a, d^c^b^a)
                    int a = (m >> 3) & 1, b = (m >> 2) & 1, c = (m >> 1) & 1, d = m & 1;
                    int P = (a << 3) | ((b ^ a) << 2) | ((c ^ b ^ a) << 1) | (d ^ c ^ b ^ a);
                    re = __shfl_sync(0xffffffffu, re, laneHi | P);
                    im = __shfl_sync(0xffffffffu, im, laneHi | P);
                }
#pragma unroll
                for (int i = 0; i < 4; i++) {   // RX
                    int str = 8 >> i;
                    float2 sc = sTrig[layer * 4 + i + 8];
                    float s = sc.x, c = sc.y;
                    float pre = __shfl_xor_sync(0xffffffffu, re, str);
                    float pim = __shfl_xor_sync(0xffffffffu, im, str);
                    float nr = fmaf(s, pim, c * re);
                    float ni = fmaf(-s, pre, c * im);
                    re = nr; im = ni;
                }
            }
            Ucol[j][m] = make_float2(re, im);
        }
        __syncthreads();
        {   // M[j][k] = sum_m conj(U[m][j]) * z_m * U[m][k]
            int j = tid >> 4, k = tid & 15;
            float ar = 0.f, ai = 0.f;
#pragma unroll
            for (int m = 0; m < 16; m++) {
                float z = (m < 8) ? 1.f : -1.f;
                float2 uj = Ucol[j][m], uk = Ucol[k][m];
                ar += z * (uj.x * uk.x + uj.y * uk.y);
                ai += z * (uj.x * uk.y - uj.y * uk.x);
            }
            Msh[j][k] = make_float2(ar, ai);
        }
        __syncthreads();
        {   // c_a = Re(Tr(M P_a)) / 16  (proven branchy form)
            int a = tid;
            float accr = 0.f;
            for (int j = 0; j < 16; j++) {
                int k = j;
                float cr = 1.f, ci = 0.f;
                for (int i = 0; i < 4; i++) {
                    int ai_ = (a >> (2 * (3 - i))) & 3;
                    int ji  = (j >> (3 - i)) & 1;
                    if (ai_ == 1) {
                        k ^= (1 << (3 - i));
                    } else if (ai_ == 2) {
                        k ^= (1 << (3 - i));
                        float nr, ni;
                        if (ji == 0) { nr = -ci; ni = cr; } else { nr = ci; ni = -cr; }
                        cr = nr; ci = ni;
                    } else if (ai_ == 3) {
                        if (ji) { cr = -cr; ci = -ci; }
                    }
                }
                float2 mm = Msh[j][k];
                accr += mm.x * cr - mm.y * ci;
            }
            float cv = accr * (1.0f / 16.0f);
            gC[a] = pk(cv, cv);
        }
        __syncthreads();
        __threadfence();
        if (tid == 0) atomicExch(&gFlagC, 1);
        return;
    }

    // ============================ PRODUCER: LUT ==============================
    if (bid < NPROD) {
        __shared__ float sW1[32], sB1[32], sW2[512], sB2[16];
        __shared__ float sW3[128], sB3[8], sW4[8], sB4;
        __shared__ float sv[130];

        if (tid < 32)                     { sW1[tid] = W1[tid]; sB1[tid] = b1[tid]; }
        else if (tid >= 64 && tid < 192)  sW3[tid - 64] = W3[tid - 64];
        else if (tid >= 192 && tid < 200) sB3[tid - 192] = b3[tid - 192];
        else if (tid >= 200 && tid < 208) sW4[tid - 200] = W4[tid - 200];
        else if (tid >= 208 && tid < 224) sB2[tid - 208] = b2[tid - 208];
        else if (tid == 224)              sB4 = b4[0];
        for (int i = tid; i < 512; i += 256) sW2[i] = W2[i];
        __syncthreads();

        if (tid <= 128) {                 // 129 points -> 128 slopes
            int i = (bid - 1) * 128 + tid;
            float q = fmaf((float)i, 2.0f / (float)TABN, -1.0f);

            float acc2[16];
#pragma unroll
            for (int k = 0; k < 16; k++) acc2[k] = sB2[k];
#pragma unroll 4
            for (int j = 0; j < 32; j++) {
                float h1j = fmaxf(fmaf(sW1[j], q, sB1[j]), 0.f);
#pragma unroll
                for (int k = 0; k < 16; k++)
                    acc2[k] = fmaf(sW2[k * 32 + j], h1j, acc2[k]);
            }
            float acc3[8];
#pragma unroll
            for (int k = 0; k < 8; k++) acc3[k] = sB3[k];
#pragma unroll 4
            for (int j = 0; j < 16; j++) {
                float h2j = fmaxf(acc2[j], 0.f);
#pragma unroll
                for (int k = 0; k < 8; k++)
                    acc3[k] = fmaf(sW3[k * 16 + j], h2j, acc3[k]);
            }
            float o = sB4;
#pragma unroll
            for (int j = 0; j < 8; j++) o = fmaf(sW4[j], fmaxf(acc3[j], 0.f), o);
            sv[tid] = 1.f / (1.f + expf(-o));
        }
        __syncthreads();
        if (tid < 128)
            gTab[(bid - 1) * 128 + tid] = make_float2(sv[tid], sv[tid + 1] - sv[tid]);
        __syncthreads();
        __threadfence();
        if (tid == 0) atomicOr(&gFlagLUT, 1 << (bid - 1));
        return;
    }

    // ============================ CONSUMERS ==================================
    // 8 samples/thread: FOUR independent packed f32x2 chains sharing each
    // coefficient load.
    __shared__ __align__(16) ulonglong2 sC[128];

    int t = (bid - NPROD) * CONSUMER_BLK + tid;
    float4 xs[8];
#pragma unroll
    for (int i = 0; i < 8; i++) xs[i] = x4[8 * t + i];

    // Bloch components per pair p, qubit i: [X,Y,Z] = [sin^2, -sin*cos, cos]
    u64 n[4][4][3];
#pragma unroll
    for (int p = 0; p < 4; p++) {
        float4 xa = xs[2 * p];
        float4 xb = xs[2 * p + 1];
        float va[4] = {xa.x, xa.y, xa.z, xa.w};
        float vb[4] = {xb.x, xb.y, xb.z, xb.w};
#pragma unroll
        for (int i = 0; i < 4; i++) {
            float sa, ca, sb, cb;
            __sincosf(va[i], &sa, &ca);
            __sincosf(vb[i], &sb, &cb);
            n[p][i][0] = pk(sa * sa, sb * sb);
            n[p][i][1] = pk(-sa * ca, -sb * cb);
            n[p][i][2] = pk(ca, cb);
        }
    }

    // wait for Pauli coeffs (fast-trig producer finishes ~1.5us in)
    if (tid == 0) {
        while (ldAcq(&gFlagC) == 0) __nanosleep(64);
    }
    __syncthreads();
    if (tid < 128) sC[tid] = ((const ulonglong2*)gC)[tid];
    __syncthreads();

    // q = Pauli tensor contraction, four independent chains share coeff loads
    u64 Q[4];
    {
        u64 acc0[4];
#pragma unroll
        for (int a0 = 0; a0 < 4; a0++) {
            u64 acc1[4];
#pragma unroll
            for (int a1 = 0; a1 < 4; a1++) {
                ulonglong2 cg[8];
#pragma unroll
                for (int a2 = 0; a2 < 4; a2++) {
                    int bidx = (a0 * 4 + a1) * 4 + a2;
                    cg[2 * a2]     = sC[2 * bidx];
                    cg[2 * a2 + 1] = sC[2 * bidx + 1];
                }
                u64 accA[4];
#pragma unroll
                for (int a2 = 0; a2 < 4; a2++) {
                    ulonglong2 c01 = cg[2 * a2];
                    ulonglong2 c23 = cg[2 * a2 + 1];
#pragma unroll
                    for (int p = 0; p < 4; p++) {
                        u64 s3 = fma2(c01.y, n[p][3][0], c01.x);
                        s3 = fma2(c23.x, n[p][3][1], s3);
                        s3 = fma2(c23.y, n[p][3][2], s3);
                        if (a2 == 0) accA[p] = s3;
                        else         accA[p] = fma2(s3, n[p][2][a2 - 1], accA[p]);
                    }
                }
#pragma unroll
                for (int p = 0; p < 4; p++) {
                    if (a1 == 0) acc1[p] = accA[p];
                    else         acc1[p] = fma2(accA[p], n[p][1][a1 - 1], acc1[p]);
                }
            }
#pragma unroll
            for (int p = 0; p < 4; p++) {
                if (a0 == 0) acc0[p] = acc1[p];
                else         acc0[p] = fma2(acc1[p], n[p][0][a0 - 1], acc0[p]);
            }
        }
#pragma unroll
        for (int p = 0; p < 4; p++) Q[p] = acc0[p];
    }

    // wait for LUT: single-thread poll, then block-wide release
    if (tid == 0) {
        while ((ldAcq(&gFlagLUT) & 0xF) != 0xF) __nanosleep(64);
    }
    __syncthreads();

    float4 ro[2];
#pragma unroll
    for (int p = 0; p < 4; p++) {
        float q0, q1;
        upk(q0, q1, Q[p]);
        float qs[2] = {q0, q1};
        float rs[2];
#pragma unroll
        for (int s = 0; s < 2; s++) {
            float idxf = fmaf(qs[s], (float)(TABN / 2), (float)(TABN / 2));
            idxf = fminf(fmaxf(idxf, 0.f), (float)TABN - 0.0005f);
            float fi = floorf(idxf);
            int i = (int)fi;
            float fr = idxf - fi;
            float2 e = __ldg(&gTab[i]);
            rs[s] = fmaf(e.y, fr, e.x);
        }
        if (p == 0) { ro[0].x = rs[0]; ro[0].y = rs[1]; }
        if (p == 1) { ro[0].z = rs[0]; ro[0].w = rs[1]; }
        if (p == 2) { ro[1].x = rs[0]; ro[1].y = rs[1]; }
        if (p == 3) { ro[1].z = rs[0]; ro[1].w = rs[1]; }
    }
    out4[2 * t]     = ro[0];
    out4[2 * t + 1] = ro[1];
}

// ---------------- launch ----------------------------------------------------
extern "C" void kernel_launch(void* const* d_in, const int* in_sizes, int n_in,
                              void* d_out, int out_size) {
    const float* x  = (const float*)d_in[0];
    const float* qw = (const float*)d_in[1];
    const float* W1 = (const float*)d_in[2];
    const float* b1 = (const float*)d_in[3];
    const float* W2 = (const float*)d_in[4];
    const float* b2 = (const float*)d_in[5];
    const float* W3 = (const float*)d_in[6];
    const float* b3 = (const float*)d_in[7];
    const float* W4 = (const float*)d_in[8];
    const float* b4 = (const float*)d_in[9];

    int nthreads = out_size / 8;                       // 8 samples per thread
    int nblocks  = NPROD + nthreads / CONSUMER_BLK;    // 5 producers + 128 consumers
    qnn_fused<<<nblocks, CONSUMER_BLK>>>((const float4*)x, (float4*)d_out, qw,
                                         W1, b1, W2, b2, W3, b3, W4, b4);
}

// round 17
// speedup vs baseline: 2.0925x; 1.0030x over previous
#include <cuda_runtime.h>

typedef unsigned long long u64;

#define TABN 512
#define NPROD 5                 // block 0 = Pauli, blocks 1..4 = LUT quarters
#define CONSUMER_BLK 256

__device__ __align__(16) u64    gC[256];      // Pauli coeffs, duplicated (c,c)
__device__ __align__(16) float2 gTab[TABN];   // (value, slope) of sigmoid(MLP(q))
__device__ int gFlagC   = 0;                  // Pauli coeffs ready
__device__ int gFlagLUT = 0;                  // bit b-1 set when LUT block b done

// ---------------- packed f32x2 helpers --------------------------------------
__device__ __forceinline__ u64 pk(float lo, float hi) {
    u64 r; asm("mov.b64 %0, {%1, %2};" : "=l"(r) : "f"(lo), "f"(hi)); return r;
}
__device__ __forceinline__ void upk(float& lo, float& hi, u64 v) {
    asm("mov.b64 {%0, %1}, %2;" : "=f"(lo), "=f"(hi) : "l"(v));
}
__device__ __forceinline__ u64 fma2(u64 a, u64 b, u64 c) {
    u64 d; asm("fma.rn.f32x2 %0, %1, %2, %3;" : "=l"(d) : "l"(a), "l"(b), "l"(c));
    return d;
}
__device__ __forceinline__ int ldAcq(const int* p) {
    int v; asm volatile("ld.acquire.gpu.global.b32 %0, [%1];" : "=r"(v) : "l"(p) : "memory");
    return v;
}

// ---------------- fused kernel ----------------------------------------------
// 8 samples/thread, strided sample mapping (thread T handles samples
// {T + j*NT}, NT = total consumer threads): every LDG.128 is lane-coalesced
// (4 lines/warp instead of 32). 128 consumer blocks + 5 producers = 133
// blocks <= 148 SMs: one CTA per SM, single balanced wave. No min-blocks
// clamp (consumer needs ~150 regs; clamping would spill — R4/R6/R14 lesson).
__global__ void __launch_bounds__(CONSUMER_BLK) qnn_fused(
        const float4* __restrict__ x4, float* __restrict__ out,
        const float* __restrict__ qw,
        const float* __restrict__ W1, const float* __restrict__ b1,
        const float* __restrict__ W2, const float* __restrict__ b2,
        const float* __restrict__ W3, const float* __restrict__ b3,
        const float* __restrict__ W4, const float* __restrict__ b4) {
    int tid = threadIdx.x;
    int bid = blockIdx.x;

    // ============================ PRODUCER: Pauli ============================
    if (bid == 0) {
        __shared__ float2 sTrig[16];      // (sin(qw/2), cos(qw/2))
        __shared__ float2 Ucol[16][16];   // Ucol[j][m] = U[m][j]
        __shared__ float2 Msh[16][16];

        if (tid < 16) {
            float s, c;
            __sincosf(0.5f * qw[tid], &s, &c);   // MUFU trig: R8-proven numerics
            sTrig[tid] = make_float2(s, c);
        }
        __syncthreads();

        {
            int j = tid >> 4, m = tid & 15;
            int laneHi = (tid & 31) & 16;
            float re = (m == j) ? 1.f : 0.f;
            float im = 0.f;
            for (int layer = 0; layer < 2; layer++) {
#pragma unroll
                for (int i = 0; i < 4; i++) {
                    int str = 8 >> i;
                    int bit = m & str;
                    {   // RY
                        float2 sc = sTrig[layer * 4 + i];
                        float s = sc.x, c = sc.y;
                        float pre = __shfl_xor_sync(0xffffffffu, re, str);
                        float pim = __shfl_xor_sync(0xffffffffu, im, str);
                        if (bit) { re = fmaf(s, pre, c * re); im = fmaf(s, pim, c * im); }
                        else     { re = fmaf(-s, pre, c * re); im = fmaf(-s, pim, c * im); }
                    }
                    {   // RZ — diagonal, no shuffle
                        float2 sc = sTrig[layer * 4 + i + 4];
                        float sz = sc.x, cz = sc.y;
                        float nr, ni;
                        if (bit) { nr = re * cz - im * sz; ni = im * cz + re * sz; }
                        else     { nr = re * cz + im * sz; ni = im * cz - re * sz; }
                        re = nr; im = ni;
                    }
                }
                {   // composed CNOTs: src bits (a, b^a, c^b^a, d^c^b^a)
                    int a = (m >> 3) & 1, b = (m >> 2) & 1, c = (m >> 1) & 1, d = m & 1;
                    int P = (a << 3) | ((b ^ a) << 2) | ((c ^ b ^ a) << 1) | (d ^ c ^ b ^ a);
                    re = __shfl_sync(0xffffffffu, re, laneHi | P);
                    im = __shfl_sync(0xffffffffu, im, laneHi | P);
                }
#pragma unroll
                for (int i = 0; i < 4; i++) {   // RX
                    int str = 8 >> i;
                    float2 sc = sTrig[layer * 4 + i + 8];
                    float s = sc.x, c = sc.y;
                    float pre = __shfl_xor_sync(0xffffffffu, re, str);
                    float pim = __shfl_xor_sync(0xffffffffu, im, str);
                    float nr = fmaf(s, pim, c * re);
                    float ni = fmaf(-s, pre, c * im);
                    re = nr; im = ni;
                }
            }
            Ucol[j][m] = make_float2(re, im);
        }
        __syncthreads();
        {   // M[j][k] = sum_m conj(U[m][j]) * z_m * U[m][k]
            int j = tid >> 4, k = tid & 15;
            float ar = 0.f, ai = 0.f;
#pragma unroll
            for (int m = 0; m < 16; m++) {
                float z = (m < 8) ? 1.f : -1.f;
                float2 uj = Ucol[j][m], uk = Ucol[k][m];
                ar += z * (uj.x * uk.x + uj.y * uk.y);
                ai += z * (uj.x * uk.y - uj.y * uk.x);
            }
            Msh[j][k] = make_float2(ar, ai);
        }
        __syncthreads();
        {   // c_a = Re(Tr(M P_a)) / 16  (proven branchy form)
            int a = tid;
            float accr = 0.f;
            for (int j = 0; j < 16; j++) {
                int k = j;
                float cr = 1.f, ci = 0.f;
                for (int i = 0; i < 4; i++) {
                    int ai_ = (a >> (2 * (3 - i))) & 3;
                    int ji  = (j >> (3 - i)) & 1;
                    if (ai_ == 1) {
                        k ^= (1 << (3 - i));
                    } else if (ai_ == 2) {
                        k ^= (1 << (3 - i));
                        float nr, ni;
                        if (ji == 0) { nr = -ci; ni = cr; } else { nr = ci; ni = -cr; }
                        cr = nr; ci = ni;
                    } else if (ai_ == 3) {
                        if (ji) { cr = -cr; ci = -ci; }
                    }
                }
                float2 mm = Msh[j][k];
                accr += mm.x * cr - mm.y * ci;
            }
            float cv = accr * (1.0f / 16.0f);
            gC[a] = pk(cv, cv);
        }
        __syncthreads();
        __threadfence();
        if (tid == 0) atomicExch(&gFlagC, 1);
        return;
    }

    // ============================ PRODUCER: LUT ==============================
    if (bid < NPROD) {
        __shared__ float sW1[32], sB1[32], sW2[512], sB2[16];
        __shared__ float sW3[128], sB3[8], sW4[8], sB4;
        __shared__ float sv[130];

        if (tid < 32)                     { sW1[tid] = W1[tid]; sB1[tid] = b1[tid]; }
        else if (tid >= 64 && tid < 192)  sW3[tid - 64] = W3[tid - 64];
        else if (tid >= 192 && tid < 200) sB3[tid - 192] = b3[tid - 192];
        else if (tid >= 200 && tid < 208) sW4[tid - 200] = W4[tid - 200];
        else if (tid >= 208 && tid < 224) sB2[tid - 208] = b2[tid - 208];
        else if (tid == 224)              sB4 = b4[0];
        for (int i = tid; i < 512; i += 256) sW2[i] = W2[i];
        __syncthreads();

        if (tid <= 128) {                 // 129 points -> 128 slopes
            int i = (bid - 1) * 128 + tid;
            float q = fmaf((float)i, 2.0f / (float)TABN, -1.0f);

            float acc2[16];
#pragma unroll
            for (int k = 0; k < 16; k++) acc2[k] = sB2[k];
#pragma unroll 4
            for (int j = 0; j < 32; j++) {
                float h1j = fmaxf(fmaf(sW1[j], q, sB1[j]), 0.f);
#pragma unroll
                for (int k = 0; k < 16; k++)
                    acc2[k] = fmaf(sW2[k * 32 + j], h1j, acc2[k]);
            }
            float acc3[8];
#pragma unroll
            for (int k = 0; k < 8; k++) acc3[k] = sB3[k];
#pragma unroll 4
            for (int j = 0; j < 16; j++) {
                float h2j = fmaxf(acc2[j], 0.f);
#pragma unroll
                for (int k = 0; k < 8; k++)
                    acc3[k] = fmaf(sW3[k * 16 + j], h2j, acc3[k]);
            }
            float o = sB4;
#pragma unroll
            for (int j = 0; j < 8; j++) o = fmaf(sW4[j], fmaxf(acc3[j], 0.f), o);
            sv[tid] = 1.f / (1.f + expf(-o));
        }
        __syncthreads();
        if (tid < 128)
            gTab[(bid - 1) * 128 + tid] = make_float2(sv[tid], sv[tid + 1] - sv[tid]);
        __syncthreads();
        __threadfence();
        if (tid == 0) atomicOr(&gFlagLUT, 1 << (bid - 1));
        return;
    }

    // ============================ CONSUMERS ==================================
    // Thread T handles samples {T + j*NT}, j=0..7 (NT = total consumer threads)
    // -> all 8 LDG.128 lane-coalesced; outputs are 8 coalesced STG.32.
    __shared__ __align__(16) ulonglong2 sC[128];

    int NT = (gridDim.x - NPROD) * CONSUMER_BLK;       // 32768
    int T  = (bid - NPROD) * CONSUMER_BLK + tid;

    float4 xs[8];
#pragma unroll
    for (int j = 0; j < 8; j++) xs[j] = x4[T + j * NT];

    // Bloch components per chain p, qubit i: [X,Y,Z] = [sin^2, -sin*cos, cos]
    // chain p packs samples (T + 2p*NT, T + (2p+1)*NT) as (lo, hi)
    u64 n[4][4][3];
#pragma unroll
    for (int p = 0; p < 4; p++) {
        float4 xa = xs[2 * p];
        float4 xb = xs[2 * p + 1];
        float va[4] = {xa.x, xa.y, xa.z, xa.w};
        float vb[4] = {xb.x, xb.y, xb.z, xb.w};
#pragma unroll
        for (int i = 0; i < 4; i++) {
            float sa, ca, sb, cb;
            __sincosf(va[i], &sa, &ca);
            __sincosf(vb[i], &sb, &cb);
            n[p][i][0] = pk(sa * sa, sb * sb);
            n[p][i][1] = pk(-sa * ca, -sb * cb);
            n[p][i][2] = pk(ca, cb);
        }
    }

    // wait for Pauli coeffs (MUFU-trig producer finishes ~1.5us in)
    if (tid == 0) {
        while (ldAcq(&gFlagC) == 0) __nanosleep(32);
    }
    __syncthreads();
    if (tid < 128) sC[tid] = ((const ulonglong2*)gC)[tid];
    __syncthreads();

    // q = Pauli tensor contraction, four independent chains share coeff loads
    u64 Q[4];
    {
        u64 acc0[4];
#pragma unroll
        for (int a0 = 0; a0 < 4; a0++) {
            u64 acc1[4];
#pragma unroll
            for (int a1 = 0; a1 < 4; a1++) {
                ulonglong2 cg[8];
#pragma unroll
                for (int a2 = 0; a2 < 4; a2++) {
                    int bidx = (a0 * 4 + a1) * 4 + a2;
                    cg[2 * a2]     = sC[2 * bidx];
                    cg[2 * a2 + 1] = sC[2 * bidx + 1];
                }
                u64 accA[4];
#pragma unroll
                for (int a2 = 0; a2 < 4; a2++) {
                    ulonglong2 c01 = cg[2 * a2];
                    ulonglong2 c23 = cg[2 * a2 + 1];
#pragma unroll
                    for (int p = 0; p < 4; p++) {
                        u64 s3 = fma2(c01.y, n[p][3][0], c01.x);
                        s3 = fma2(c23.x, n[p][3][1], s3);
                        s3 = fma2(c23.y, n[p][3][2], s3);
                        if (a2 == 0) accA[p] = s3;
                        else         accA[p] = fma2(s3, n[p][2][a2 - 1], accA[p]);
                    }
                }
#pragma unroll
                for (int p = 0; p < 4; p++) {
                    if (a1 == 0) acc1[p] = accA[p];
                    else         acc1[p] = fma2(accA[p], n[p][1][a1 - 1], acc1[p]);
                }
            }
#pragma unroll
            for (int p = 0; p < 4; p++) {
                if (a0 == 0) acc0[p] = acc1[p];
                else         acc0[p] = fma2(acc1[p], n[p][0][a0 - 1], acc0[p]);
            }
        }
#pragma unroll
        for (int p = 0; p < 4; p++) Q[p] = acc0[p];
    }

    // wait for LUT: single-thread poll, then block-wide release
    if (tid == 0) {
        while ((ldAcq(&gFlagLUT) & 0xF) != 0xF) __nanosleep(32);
    }
    __syncthreads();

#pragma unroll
    for (int p = 0; p < 4; p++) {
        float q0, q1;
        upk(q0, q1, Q[p]);
        float qs[2] = {q0, q1};
#pragma unroll
        for (int s = 0; s < 2; s++) {
            float idxf = fmaf(qs[s], (float)(TABN / 2), (float)(TABN / 2));
            idxf = fminf(fmaxf(idxf, 0.f), (float)TABN - 0.0005f);
            float fi = floorf(idxf);
            int i = (int)fi;
            float fr = idxf - fi;
            float2 e = __ldg(&gTab[i]);
            out[T + (2 * p + s) * NT] = fmaf(e.y, fr, e.x);
        }
    }
}

// ---------------- launch ----------------------------------------------------
extern "C" void kernel_launch(void* const* d_in, const int* in_sizes, int n_in,
                              void* d_out, int out_size) {
    const float* x  = (const float*)d_in[0];
    const float* qw = (const float*)d_in[1];
    const float* W1 = (const float*)d_in[2];
    const float* b1 = (const float*)d_in[3];
    const float* W2 = (const float*)d_in[4];
    const float* b2 = (const float*)d_in[5];
    const float* W3 = (const float*)d_in[6];
    const float* b3 = (const float*)d_in[7];
    const float* W4 = (const float*)d_in[8];
    const float* b4 = (const float*)d_in[9];

    int nthreads = out_size / 8;                       // 8 samples per thread
    int nblocks  = NPROD + nthreads / CONSUMER_BLK;    // 5 producers + 128 consumers
    qnn_fused<<<nblocks, CONSUMER_BLK>>>((const float4*)x, (float*)d_out, qw,
                                         W1, b1, W2, b2, W3, b3, W4, b4);
}